// round 8
// baseline (speedup 1.0000x reference)
#include <cuda_runtime.h>
#include <cstddef>
#include <cstdint>

#define N_DIM 4096
#define B_DIM 2048
#define RANK  4
#define INV_N (1.0f / 4096.0f)

// erf(alpha*x) ~= tanh( x * (1 + x^2*(C3P + C5P*x^2)) )   [alpha folded: c1'=1]
#define ERF_C3P 0.0721781f
#define ERF_C5P (-0.000887f)

// Scratch: rows 0..3 = s[r][B] (pre-scaled by 1/N), row 4 = y[B] (pre-scaled)
__device__ __align__(16) float g_acc[5 * B_DIM];

typedef unsigned long long u64;

__device__ __forceinline__ u64 pack2(float lo, float hi) {
    u64 r; asm("mov.b64 %0, {%1,%2};" : "=l"(r) : "f"(lo), "f"(hi)); return r;
}
__device__ __forceinline__ void unpack2(u64 v, float& lo, float& hi) {
    asm("mov.b64 {%0,%1}, %2;" : "=f"(lo), "=f"(hi) : "l"(v));
}
__device__ __forceinline__ u64 fma2(u64 a, u64 b, u64 c) {
    u64 d; asm("fma.rn.f32x2 %0, %1, %2, %3;" : "=l"(d) : "l"(a), "l"(b), "l"(c)); return d;
}
__device__ __forceinline__ u64 add2(u64 a, u64 b) {
    u64 d; asm("add.rn.f32x2 %0, %1, %2;" : "=l"(d) : "l"(a), "l"(b)); return d;
}
__device__ __forceinline__ u64 mul2(u64 a, u64 b) {
    u64 d; asm("mul.rn.f32x2 %0, %1, %2;" : "=l"(d) : "l"(a), "l"(b)); return d;
}
__device__ __forceinline__ float tanh_fast(float x) {
    float y; asm("tanh.approx.f32 %0, %1;" : "=f"(y) : "f"(x)); return y;
}

__device__ __forceinline__ u64 phi2(u64 X, u64 C3, u64 C5, u64 ONE) {
    u64 S = mul2(X, X);
    u64 K = fma2(C5, S, C3);
    K = fma2(K, S, ONE);
    u64 A = mul2(K, X);
    float a0, a1; unpack2(A, a0, a1);
    return pack2(tanh_fast(a0), tanh_fast(a1));
}

// ---------------------------------------------------------------------------
// Reduce: s[j][b] += sum_n (v[n][j]/N) * phi(h[n][b]);  same for y with z/N.
// Block = 4 row-subgroups (ty) x 64 column-quads (tx). Each thread does 8 rows.
// Grid (8, 128) = 1024 blocks. Intra-block SMEM reduce, then red.global.add.v4.
// ---------------------------------------------------------------------------
#define BLK_ROWS 32
#define R_PER_T  8
#define QUADS_PB 64

__global__ void reduce_kernel(const float* __restrict__ h,
                              const float* __restrict__ v,
                              const float* __restrict__ z) {
    __shared__ u64 svz[BLK_ROWS][5];
    __shared__ u64 s_red[3][QUADS_PB][5][2];

    const int tid = threadIdx.x;
    const int ty  = tid >> 6;
    const int tx  = tid & 63;
    const int n0b = blockIdx.y * BLK_ROWS;

    if (tid < BLK_ROWS * 5) {
        int r = tid / 5, j = tid % 5;
        float val = ((j < 4) ? v[(size_t)(n0b + r) * RANK + j] : z[n0b + r]) * INV_N;
        svz[r][j] = pack2(val, val);
    }
    __syncthreads();

    const u64 C3  = pack2(ERF_C3P, ERF_C3P);
    const u64 C5  = pack2(ERF_C5P, ERF_C5P);
    const u64 ONE = pack2(1.0f, 1.0f);

    const int q  = blockIdx.x * QUADS_PB + tx;
    const int b0 = q * 4;
    const int n0 = n0b + ty * R_PER_T;

    u64 acc0[5], acc1[5];
    #pragma unroll
    for (int j = 0; j < 5; j++) { acc0[j] = 0ull; acc1[j] = 0ull; }

    #pragma unroll
    for (int rb = 0; rb < R_PER_T; rb += 4) {
        float4 hv[4];
        #pragma unroll
        for (int i = 0; i < 4; i++)
            hv[i] = *reinterpret_cast<const float4*>(h + (size_t)(n0 + rb + i) * B_DIM + b0);
        #pragma unroll
        for (int i = 0; i < 4; i++) {
            const int r = ty * R_PER_T + rb + i;
            u64 P0 = phi2(pack2(hv[i].x, hv[i].y), C3, C5, ONE);
            u64 P1 = phi2(pack2(hv[i].z, hv[i].w), C3, C5, ONE);
            #pragma unroll
            for (int j = 0; j < 5; j++) {
                u64 w = svz[r][j];
                acc0[j] = fma2(w, P0, acc0[j]);
                acc1[j] = fma2(w, P1, acc1[j]);
            }
        }
    }

    if (ty > 0) {
        #pragma unroll
        for (int j = 0; j < 5; j++) {
            s_red[ty - 1][tx][j][0] = acc0[j];
            s_red[ty - 1][tx][j][1] = acc1[j];
        }
    }
    __syncthreads();
    if (ty == 0) {
        #pragma unroll
        for (int j = 0; j < 5; j++) {
            u64 a = acc0[j], b = acc1[j];
            #pragma unroll
            for (int t = 0; t < 3; t++) {
                a = add2(a, s_red[t][tx][j][0]);
                b = add2(b, s_red[t][tx][j][1]);
            }
            float a0, a1, a2, a3;
            unpack2(a, a0, a1);
            unpack2(b, a2, a3);
            float* p = g_acc + j * B_DIM + b0;
            asm volatile("red.global.add.v4.f32 [%0], {%1,%2,%3,%4};"
                         :: "l"(p), "f"(a0), "f"(a1), "f"(a2), "f"(a3) : "memory");
        }
    }
}

// ---------------------------------------------------------------------------
// Finalize (TMA-store version):
//   h_new[n][b] = m[n]*x_t[b] + sum_j u[n][j]*s[j][b]   (s pre-scaled by 1/N)
// Block handles 8 FULL rows (8 x 2048 floats = 64 KB, contiguous in out):
//   compute -> stage in dynamic SMEM -> ONE cp.async.bulk 64 KB store.
// 512 blocks, 256 threads; each thread owns column-quads {tid, tid+256}.
// Block 0 also emits y[B] via regular stores.
// ---------------------------------------------------------------------------
#define FB_ROWS 8
#define FB_THREADS 256
#define STAGE_BYTES (FB_ROWS * B_DIM * 4)   // 65536

__global__ void __launch_bounds__(FB_THREADS)
finalize_kernel(const float* __restrict__ x_t,
                const float* __restrict__ u,
                const float* __restrict__ m,
                float* __restrict__ out) {
    extern __shared__ float s_stage[];   // [FB_ROWS][B_DIM]

    const int tid = threadIdx.x;
    const int n0  = blockIdx.x * FB_ROWS;
    const int BQ  = B_DIM / 4;

    const float4* u4 = reinterpret_cast<const float4*>(u);
    const float4* ga = reinterpret_cast<const float4*>(g_acc);

    float4 a[2], b[2], c[2], d[2], xt[2];
    #pragma unroll
    for (int qi = 0; qi < 2; qi++) {
        const int q = tid + qi * FB_THREADS;
        a[qi]  = __ldg(ga + 0 * BQ + q);
        b[qi]  = __ldg(ga + 1 * BQ + q);
        c[qi]  = __ldg(ga + 2 * BQ + q);
        d[qi]  = __ldg(ga + 3 * BQ + q);
        xt[qi] = __ldg(reinterpret_cast<const float4*>(x_t) + q);
    }

    #pragma unroll
    for (int r = 0; r < FB_ROWS; r++) {
        const float4 uv = __ldg(u4 + n0 + r);      // warp-uniform broadcast
        const float  mm = __ldg(m + n0 + r);
        #pragma unroll
        for (int qi = 0; qi < 2; qi++) {
            const int q = tid + qi * FB_THREADS;
            float4 o;
            o.x = fmaf(uv.x, a[qi].x, fmaf(uv.y, b[qi].x, fmaf(uv.z, c[qi].x, fmaf(uv.w, d[qi].x, mm * xt[qi].x))));
            o.y = fmaf(uv.x, a[qi].y, fmaf(uv.y, b[qi].y, fmaf(uv.z, c[qi].y, fmaf(uv.w, d[qi].y, mm * xt[qi].y))));
            o.z = fmaf(uv.x, a[qi].z, fmaf(uv.y, b[qi].z, fmaf(uv.z, c[qi].z, fmaf(uv.w, d[qi].z, mm * xt[qi].z))));
            o.w = fmaf(uv.x, a[qi].w, fmaf(uv.y, b[qi].w, fmaf(uv.z, c[qi].w, fmaf(uv.w, d[qi].w, mm * xt[qi].w))));
            *reinterpret_cast<float4*>(s_stage + r * B_DIM + q * 4) = o;
        }
    }

    __syncthreads();

    if (tid == 0) {
        // order generic-proxy STS before async-proxy bulk read of SMEM
        asm volatile("fence.proxy.async.shared::cta;" ::: "memory");
        uint32_t saddr;
        asm("{ .reg .u64 t; cvta.to.shared.u64 t, %1; cvt.u32.u64 %0, t; }"
            : "=r"(saddr) : "l"(s_stage));
        float* gdst = out + B_DIM + (size_t)n0 * B_DIM;
        asm volatile("cp.async.bulk.global.shared::cta.bulk_group [%0], [%1], %2;"
                     :: "l"(gdst), "r"(saddr), "r"((uint32_t)STAGE_BYTES) : "memory");
        asm volatile("cp.async.bulk.commit_group;" ::: "memory");
        asm volatile("cp.async.bulk.wait_group 0;" ::: "memory");
    }

    if (blockIdx.x == 0) {   // emit y (already scaled)
        #pragma unroll
        for (int qi = 0; qi < 2; qi++) {
            const int q = tid + qi * FB_THREADS;
            reinterpret_cast<float4*>(out)[q] = __ldg(ga + 4 * BQ + q);
        }
    }
}

// ---------------------------------------------------------------------------
// Launch. Inputs: x_t[B], h[N*B], m[N], u[N*4], v[N*4], z[N].
// Output: [ y (B) | h_new (N*B) ] float32.
// ---------------------------------------------------------------------------
extern "C" void kernel_launch(void* const* d_in, const int* in_sizes, int n_in,
                              void* d_out, int out_size) {
    const float* x_t = (const float*)d_in[0];
    const float* h   = (const float*)d_in[1];
    const float* m   = (const float*)d_in[2];
    const float* u   = (const float*)d_in[3];
    const float* v   = (const float*)d_in[4];
    const float* z   = (const float*)d_in[5];
    float* out = (float*)d_out;
    (void)in_sizes; (void)n_in; (void)out_size;

    static bool attr_set = false;
    if (!attr_set) {
        cudaFuncSetAttribute(finalize_kernel,
                             cudaFuncAttributeMaxDynamicSharedMemorySize, STAGE_BYTES);
        attr_set = true;
    }

    void* acc_ptr = nullptr;
    cudaGetSymbolAddress(&acc_ptr, g_acc);
    cudaMemsetAsync(acc_ptr, 0, 5 * B_DIM * sizeof(float));

    dim3 rgrid(B_DIM / (QUADS_PB * 4), N_DIM / BLK_ROWS);   // (8, 128) = 1024
    reduce_kernel<<<rgrid, 256>>>(h, v, z);

    finalize_kernel<<<N_DIM / FB_ROWS, FB_THREADS, STAGE_BYTES>>>(x_t, u, m, out);
}

// round 9
// speedup vs baseline: 1.0017x; 1.0017x over previous
#include <cuda_runtime.h>
#include <cstddef>
#include <cstdint>

#define N_DIM 4096
#define B_DIM 2048
#define RANK  4
#define INV_N (1.0f / 4096.0f)

// erf(alpha*x) ~= tanh( x * (1 + x^2*(C3P + C5P*x^2)) )   [alpha folded: c1'=1]
#define ERF_C3P 0.0721781f
#define ERF_C5P (-0.000887f)

// Scratch: rows 0..3 = s[r][B] (pre-scaled by 1/N), row 4 = y[B] (pre-scaled)
__device__ __align__(16) float g_acc[5 * B_DIM];

typedef unsigned long long u64;

__device__ __forceinline__ u64 pack2(float lo, float hi) {
    u64 r; asm("mov.b64 %0, {%1,%2};" : "=l"(r) : "f"(lo), "f"(hi)); return r;
}
__device__ __forceinline__ void unpack2(u64 v, float& lo, float& hi) {
    asm("mov.b64 {%0,%1}, %2;" : "=f"(lo), "=f"(hi) : "l"(v));
}
__device__ __forceinline__ u64 fma2(u64 a, u64 b, u64 c) {
    u64 d; asm("fma.rn.f32x2 %0, %1, %2, %3;" : "=l"(d) : "l"(a), "l"(b), "l"(c)); return d;
}
__device__ __forceinline__ u64 add2(u64 a, u64 b) {
    u64 d; asm("add.rn.f32x2 %0, %1, %2;" : "=l"(d) : "l"(a), "l"(b)); return d;
}
__device__ __forceinline__ u64 mul2(u64 a, u64 b) {
    u64 d; asm("mul.rn.f32x2 %0, %1, %2;" : "=l"(d) : "l"(a), "l"(b)); return d;
}
__device__ __forceinline__ float tanh_fast(float x) {
    float y; asm("tanh.approx.f32 %0, %1;" : "=f"(y) : "f"(x)); return y;
}

__device__ __forceinline__ u64 phi2(u64 X, u64 C3, u64 C5, u64 ONE) {
    u64 S = mul2(X, X);
    u64 K = fma2(C5, S, C3);
    K = fma2(K, S, ONE);
    u64 A = mul2(K, X);
    float a0, a1; unpack2(A, a0, a1);
    return pack2(tanh_fast(a0), tanh_fast(a1));
}

// ---------------------------------------------------------------------------
// Reduce: s[j][b] += sum_n (v[n][j]/N) * phi(h[n][b]);  same for y with z/N.
// Block = 4 row-subgroups (ty) x 64 column-quads (tx). Each thread does 8 rows.
// Grid (8, 128) = 1024 blocks. Intra-block SMEM reduce, then red.global.add.v4.
// ---------------------------------------------------------------------------
#define BLK_ROWS 32
#define R_PER_T  8
#define QUADS_PB 64

__global__ void reduce_kernel(const float* __restrict__ h,
                              const float* __restrict__ v,
                              const float* __restrict__ z) {
    __shared__ u64 svz[BLK_ROWS][5];
    __shared__ u64 s_red[3][QUADS_PB][5][2];

    const int tid = threadIdx.x;
    const int ty  = tid >> 6;
    const int tx  = tid & 63;
    const int n0b = blockIdx.y * BLK_ROWS;

    if (tid < BLK_ROWS * 5) {
        int r = tid / 5, j = tid % 5;
        float val = ((j < 4) ? v[(size_t)(n0b + r) * RANK + j] : z[n0b + r]) * INV_N;
        svz[r][j] = pack2(val, val);
    }
    __syncthreads();

    const u64 C3  = pack2(ERF_C3P, ERF_C3P);
    const u64 C5  = pack2(ERF_C5P, ERF_C5P);
    const u64 ONE = pack2(1.0f, 1.0f);

    const int q  = blockIdx.x * QUADS_PB + tx;
    const int b0 = q * 4;
    const int n0 = n0b + ty * R_PER_T;

    u64 acc0[5], acc1[5];
    #pragma unroll
    for (int j = 0; j < 5; j++) { acc0[j] = 0ull; acc1[j] = 0ull; }

    #pragma unroll
    for (int rb = 0; rb < R_PER_T; rb += 4) {
        float4 hv[4];
        #pragma unroll
        for (int i = 0; i < 4; i++)
            hv[i] = *reinterpret_cast<const float4*>(h + (size_t)(n0 + rb + i) * B_DIM + b0);
        #pragma unroll
        for (int i = 0; i < 4; i++) {
            const int r = ty * R_PER_T + rb + i;
            u64 P0 = phi2(pack2(hv[i].x, hv[i].y), C3, C5, ONE);
            u64 P1 = phi2(pack2(hv[i].z, hv[i].w), C3, C5, ONE);
            #pragma unroll
            for (int j = 0; j < 5; j++) {
                u64 w = svz[r][j];
                acc0[j] = fma2(w, P0, acc0[j]);
                acc1[j] = fma2(w, P1, acc1[j]);
            }
        }
    }

    if (ty > 0) {
        #pragma unroll
        for (int j = 0; j < 5; j++) {
            s_red[ty - 1][tx][j][0] = acc0[j];
            s_red[ty - 1][tx][j][1] = acc1[j];
        }
    }
    __syncthreads();
    if (ty == 0) {
        #pragma unroll
        for (int j = 0; j < 5; j++) {
            u64 a = acc0[j], b = acc1[j];
            #pragma unroll
            for (int t = 0; t < 3; t++) {
                a = add2(a, s_red[t][tx][j][0]);
                b = add2(b, s_red[t][tx][j][1]);
            }
            float a0, a1, a2, a3;
            unpack2(a, a0, a1);
            unpack2(b, a2, a3);
            float* p = g_acc + j * B_DIM + b0;
            asm volatile("red.global.add.v4.f32 [%0], {%1,%2,%3,%4};"
                         :: "l"(p), "f"(a0), "f"(a1), "f"(a2), "f"(a3) : "memory");
        }
    }
}

// ---------------------------------------------------------------------------
// Finalize (pipelined TMA-store version):
//   h_new[n][b] = m[n]*x_t[b] + sum_j u[n][j]*s[j][b]   (s pre-scaled by 1/N)
// Block = 8 full rows x 2048 cols, 256 threads (2 quads/thread).
// Ring of 4 x 8KB row buffers in SMEM; per row: compute -> STS -> fence ->
// cp.async.bulk (8KB) -> commit_group. wait_group 3 gates buffer reuse;
// wait_group 0 only at block exit. Stores ride the TMA engine, not LSU/L1tex.
// ---------------------------------------------------------------------------
#define FB_ROWS 8
#define FB_THREADS 256
#define STAGES 4
#define ROW_BYTES (B_DIM * 4)                 // 8192
#define STAGE_BYTES (STAGES * ROW_BYTES)      // 32768

__global__ void __launch_bounds__(FB_THREADS)
finalize_kernel(const float* __restrict__ x_t,
                const float* __restrict__ u,
                const float* __restrict__ m,
                float* __restrict__ out) {
    extern __shared__ float s_stage[];   // [STAGES][B_DIM]

    const int tid = threadIdx.x;
    const int n0  = blockIdx.x * FB_ROWS;
    const int BQ  = B_DIM / 4;

    const float4* u4 = reinterpret_cast<const float4*>(u);
    const float4* ga = reinterpret_cast<const float4*>(g_acc);

    float4 a[2], b[2], c[2], d[2], xt[2];
    #pragma unroll
    for (int qi = 0; qi < 2; qi++) {
        const int q = tid + qi * FB_THREADS;
        a[qi]  = __ldg(ga + 0 * BQ + q);
        b[qi]  = __ldg(ga + 1 * BQ + q);
        c[qi]  = __ldg(ga + 2 * BQ + q);
        d[qi]  = __ldg(ga + 3 * BQ + q);
        xt[qi] = __ldg(reinterpret_cast<const float4*>(x_t) + q);
    }

    float* gdst_base = out + B_DIM + (size_t)n0 * B_DIM;

    #pragma unroll
    for (int r = 0; r < FB_ROWS; r++) {
        if (r >= STAGES) {
            // make sure the bulk store reading buf[r % STAGES] has completed
            if (tid == 0)
                asm volatile("cp.async.bulk.wait_group %0;" :: "n"(STAGES - 1) : "memory");
            __syncthreads();
        }
        float* buf = s_stage + (r & (STAGES - 1)) * B_DIM;

        const float4 uv = __ldg(u4 + n0 + r);      // warp-uniform broadcast
        const float  mm = __ldg(m + n0 + r);
        #pragma unroll
        for (int qi = 0; qi < 2; qi++) {
            const int q = tid + qi * FB_THREADS;
            float4 o;
            o.x = fmaf(uv.x, a[qi].x, fmaf(uv.y, b[qi].x, fmaf(uv.z, c[qi].x, fmaf(uv.w, d[qi].x, mm * xt[qi].x))));
            o.y = fmaf(uv.x, a[qi].y, fmaf(uv.y, b[qi].y, fmaf(uv.z, c[qi].y, fmaf(uv.w, d[qi].y, mm * xt[qi].y))));
            o.z = fmaf(uv.x, a[qi].z, fmaf(uv.y, b[qi].z, fmaf(uv.z, c[qi].z, fmaf(uv.w, d[qi].z, mm * xt[qi].z))));
            o.w = fmaf(uv.x, a[qi].w, fmaf(uv.y, b[qi].w, fmaf(uv.z, c[qi].w, fmaf(uv.w, d[qi].w, mm * xt[qi].w))));
            *reinterpret_cast<float4*>(buf + q * 4) = o;
        }

        __syncthreads();
        if (tid == 0) {
            asm volatile("fence.proxy.async.shared::cta;" ::: "memory");
            uint32_t saddr;
            asm("{ .reg .u64 t; cvta.to.shared.u64 t, %1; cvt.u32.u64 %0, t; }"
                : "=r"(saddr) : "l"(buf));
            asm volatile("cp.async.bulk.global.shared::cta.bulk_group [%0], [%1], %2;"
                         :: "l"(gdst_base + (size_t)r * B_DIM), "r"(saddr),
                            "r"((uint32_t)ROW_BYTES) : "memory");
            asm volatile("cp.async.bulk.commit_group;" ::: "memory");
        }
    }

    if (blockIdx.x == 0) {   // emit y (already scaled) via plain stores (8 KB)
        #pragma unroll
        for (int qi = 0; qi < 2; qi++) {
            const int q = tid + qi * FB_THREADS;
            reinterpret_cast<float4*>(out)[q] = __ldg(ga + 4 * BQ + q);
        }
    }

    // smem must stay valid until all bulk stores complete
    if (tid == 0)
        asm volatile("cp.async.bulk.wait_group 0;" ::: "memory");
    __syncthreads();
}

// ---------------------------------------------------------------------------
// Launch. Inputs: x_t[B], h[N*B], m[N], u[N*4], v[N*4], z[N].
// Output: [ y (B) | h_new (N*B) ] float32.
// ---------------------------------------------------------------------------
extern "C" void kernel_launch(void* const* d_in, const int* in_sizes, int n_in,
                              void* d_out, int out_size) {
    const float* x_t = (const float*)d_in[0];
    const float* h   = (const float*)d_in[1];
    const float* m   = (const float*)d_in[2];
    const float* u   = (const float*)d_in[3];
    const float* v   = (const float*)d_in[4];
    const float* z   = (const float*)d_in[5];
    float* out = (float*)d_out;
    (void)in_sizes; (void)n_in; (void)out_size;

    static bool attr_set = false;
    if (!attr_set) {
        cudaFuncSetAttribute(finalize_kernel,
                             cudaFuncAttributeMaxDynamicSharedMemorySize, STAGE_BYTES);
        attr_set = true;
    }

    void* acc_ptr = nullptr;
    cudaGetSymbolAddress(&acc_ptr, g_acc);
    cudaMemsetAsync(acc_ptr, 0, 5 * B_DIM * sizeof(float));

    dim3 rgrid(B_DIM / (QUADS_PB * 4), N_DIM / BLK_ROWS);   // (8, 128) = 1024
    reduce_kernel<<<rgrid, 256>>>(h, v, z);

    finalize_kernel<<<N_DIM / FB_ROWS, FB_THREADS, STAGE_BYTES>>>(x_t, u, m, out);
}